// round 15
// baseline (speedup 1.0000x reference)
#include <cuda_runtime.h>
#include <cstdint>

// Problem constants
#define N_NODES 20000
#define N_EDGES 320000
#define F_IN    64
#define H_DIM   256
#define S_DIM   32
#define L_DIM   128
#define B_BATCH 16
#define EPSF    1e-9f

// ===================== helpers =====================
__device__ __forceinline__ uint32_t smem_u32(const void* p) {
    uint32_t a;
    asm("{ .reg .u64 t; cvta.to.shared.u64 t, %1; cvt.u32.u64 %0, t; }" : "=r"(a) : "l"(p));
    return a;
}
__device__ __forceinline__ uint32_t f2tf32(float f) {
    uint32_t r;
    asm("cvt.rna.tf32.f32 %0, %1;" : "=r"(r) : "f"(f));
    return r;
}
__device__ __forceinline__ void mma8(float* c, const uint32_t* a, uint32_t b0, uint32_t b1) {
    asm volatile(
        "mma.sync.aligned.m16n8k8.row.col.f32.tf32.tf32.f32 "
        "{%0,%1,%2,%3}, {%4,%5,%6,%7}, {%8,%9}, {%0,%1,%2,%3};"
        : "+f"(c[0]), "+f"(c[1]), "+f"(c[2]), "+f"(c[3])
        : "r"(a[0]), "r"(a[1]), "r"(a[2]), "r"(a[3]), "r"(b0), "r"(b1));
}
__device__ __forceinline__ void ldsm4(uint32_t* r, uint32_t addr) {
    asm volatile("ldmatrix.sync.aligned.m8n8.x4.shared.b16 {%0,%1,%2,%3}, [%4];"
                 : "=r"(r[0]), "=r"(r[1]), "=r"(r[2]), "=r"(r[3]) : "r"(addr));
}
__device__ __forceinline__ void red2(float* addr, float v0, float v1) {
    asm volatile("red.global.add.v2.f32 [%0], {%1, %2};"
                 :: "l"(addr), "f"(v0), "f"(v1) : "memory");
}

// ===================== device scratch =====================
__device__ float d_XAB[(size_t)N_NODES * 512];   // [n][0:256]=XA, [256:512]=XB
__device__ float d_HS1[N_NODES * H_DIM];
__device__ float d_HS2[N_NODES * H_DIM];
__device__ float d_ACC[N_NODES * H_DIM];
__device__ float d_XLN[N_NODES * H_DIM];
__device__ float d_X2[N_NODES * H_DIM];
__device__ float d_T1[N_NODES * H_DIM];
__device__ float d_LG[N_NODES * S_DIM];
__device__ float d_degf[N_NODES];
__device__ float d_pooled[B_BATCH * S_DIM * H_DIM];
__device__ float d_TO[B_BATCH * S_DIM * H_DIM];
__device__ float d_colsum[S_DIM];
__device__ float d_entsum[1];
__device__ int   d_bstart[B_BATCH + 1];
// transposed (tf32-rounded) weights [outN][K]
__device__ float d_WT1[512 * 64];     // layer-1 w1 (both halves)
__device__ float d_WT2[256 * 256];
__device__ float d_WT3[256 * 256];
__device__ float d_WT4[512 * 256];    // layer-2 w1 (both halves)
__device__ float d_WT5[256 * 256];
__device__ float d_WT6[256 * 256];
__device__ float d_WTA[256 * 256];
__device__ float d_WTO[256 * 256];

// ===================== fused zero =====================
struct ZeroPars { float* p[6]; int n[6]; };
__global__ void zero_all(ZeroPars zp) {
    int r = blockIdx.y;
    float* p = zp.p[r];
    int n = zp.n[r];
    int i = blockIdx.x * blockDim.x + threadIdx.x;
    int st = gridDim.x * blockDim.x;
    for (; i < n; i += st) p[i] = 0.f;
}

__global__ void deg_kernel(const int* __restrict__ dst, float* __restrict__ degf) {
    int i = blockIdx.x * blockDim.x + threadIdx.x;
    int st = gridDim.x * blockDim.x;
    for (; i < N_EDGES; i += st) atomicAdd(&degf[dst[i]], 1.f);
}

// ===================== batched transpose (tf32 round) =====================
struct TransPars { const float* src[10]; float* dst[10]; int R[10]; };
__global__ void transpose_all(TransPars tp) {
    __shared__ float t[32][33];
    int m = blockIdx.z;
    const float* in = tp.src[m];
    float* out = tp.dst[m];
    int R = tp.R[m];
    int c0 = blockIdx.x * 32, r0 = blockIdx.y * 32;
    if (r0 >= R) return;
    for (int j = threadIdx.y; j < 32; j += 8) {
        int r = r0 + j, c = c0 + threadIdx.x;
        t[j][threadIdx.x] = (r < R) ? in[(size_t)r * 256 + c] : 0.f;
    }
    __syncthreads();
    for (int j = threadIdx.y; j < 32; j += 8) {
        int oc = c0 + j, orr = r0 + threadIdx.x;
        if (orr < R)
            out[(size_t)oc * R + orr] = __uint_as_float(f2tf32(t[threadIdx.x][j]));
    }
}

// ===================== tf32 mma.sync GEMM (2-stage, R9 schedule) ==============
// CTA tile MTILE(M) x NTILE(N), grid.y picks the NTILE-col block. K chunks of 32.
// 8 warps: WM_CNT = MTILE/32 M-warps x (8/WM_CNT) N-warps, warp n-width WNW.
// GATHER: A row = relu(XA[gdst*XSTR] + XB[gsrc*XSTR] + bpre).
// SCATTER: epilogue red.v2 into C[gdst].
// Smem stride 36 floats: conflict-free ldmatrix.
// A staging: 8 threads/row x 16B each, MTILE/32 passes (full 128B wavefronts).
template<int GATHER, int SCATTER, int RELU_OUT, int ADD_BIAS, int KLEN,
         int CSTR = 256, int XSTR = 256, int MTILE = 128, int NTILE = 128>
__global__ void __launch_bounds__(256, 2) mma_gemm(
    const float* __restrict__ A, int M,
    const float* __restrict__ XA, const float* __restrict__ XB,
    const float* __restrict__ bpre,
    const int* __restrict__ gsrc, const int* __restrict__ gdst,
    const float* __restrict__ WT,   // [outN][KLEN] K-major, tf32-rounded
    const float* __restrict__ bias,
    float* __restrict__ C)
{
    constexpr int WM_CNT  = MTILE / 32;         // 4 or 2
    constexpr int WN_CNT  = 8 / WM_CNT;         // 2 or 4
    constexpr int WNW     = NTILE / WN_CNT;     // warp n-width (64 here)
    constexpr int NT      = WNW / 8;            // 8
    constexpr int PASSES  = MTILE / 32;         // A staging passes (8 thr/row)
    constexpr int BROWS   = NTILE / 128;        // B row-groups per thread: 1 or 2
    constexpr int ASLOT_A = MTILE * 36;
    constexpr int ASLOT_B = NTILE * 36;

    extern __shared__ float sm[];
    float* sA = sm;                           // 2 * ASLOT_A
    float* sB = sm + 2 * ASLOT_A;             // 2 * ASLOT_B
    int* sdst = (int*)(sm + 2 * ASLOT_A + 2 * ASLOT_B);
    int* ssrc = sdst + MTILE;

    const int tid  = threadIdx.x;
    const int lane = tid & 31;
    const int wid  = tid >> 5;
    const int wm = wid % WM_CNT;
    const int wn = wid / WM_CNT;
    const int lr = lane >> 2;
    const int lc = lane & 3;
    const int row0 = blockIdx.x * MTILE;
    const int col0 = blockIdx.y * NTILE;
    constexpr int NCH = KLEN / 32;

    if ((GATHER || SCATTER) && tid < MTILE) {
        sdst[tid] = gdst[row0 + tid];
        if (GATHER) ssrc[tid] = gsrc[row0 + tid];
    }
    if (GATHER || SCATTER) __syncthreads();

    // A staging mapping: 8 threads per row, 16B (4 floats) per thread.
    const int srow = tid >> 3;    // 0..31 (row within pass)
    const int sseg = tid & 7;     // 0..7 (16B segment within 128B chunk-row)
    const int bn   = tid >> 1;
    const int bkh  = (tid & 1) << 4;
    const uint32_t sA_addr = smem_u32(sA);
    const uint32_t sB_addr = smem_u32(sB);
    const float* WTb = WT + (size_t)(col0 + bn) * KLEN + bkh;

    // ldmatrix per-thread base byte offsets (group = lane>>3, rif = lane&7)
    const int grp = lane >> 3;
    const int rif = lane & 7;
    const uint32_t aLdm = sA_addr
        + (uint32_t)(wm * 32 + (grp & 1) * 8 + rif) * 144u + (uint32_t)(grp >> 1) * 16u;
    const uint32_t bLdm = sB_addr
        + (uint32_t)(wn * WNW + (grp >> 1) * 8 + rif) * 144u + (uint32_t)(grp & 1) * 16u;

    float4 ra[PASSES], rb4[PASSES];

#define ISSUE_B(c, buf)                                                          \
    do {                                                                         \
        _Pragma("unroll")                                                        \
        for (int rr = 0; rr < BROWS; rr++) {                                     \
            uint32_t dstb = sB_addr                                              \
                + (uint32_t)((buf) * ASLOT_B + (bn + rr * 128) * 36 + bkh) * 4u; \
            const float* srcb = WTb + (size_t)rr * 128 * KLEN + (c) * 32;        \
            _Pragma("unroll")                                                    \
            for (int i = 0; i < 4; i++)                                          \
                asm volatile("cp.async.cg.shared.global [%0], [%1], 16;" ::      \
                             "r"(dstb + (uint32_t)i * 16u), "l"(srcb + i * 4) : "memory"); \
        }                                                                        \
        asm volatile("cp.async.commit_group;" ::: "memory");                     \
    } while (0)

#define LOAD_A(c)                                                                \
    do {                                                                         \
        int kg = (c) * 32 + sseg * 4;                                            \
        _Pragma("unroll")                                                        \
        for (int p = 0; p < PASSES; p++) {                                       \
            int row = p * 32 + srow;                                             \
            if (GATHER) {                                                        \
                ra[p]  = *(const float4*)(XA + (size_t)sdst[row] * XSTR + kg);   \
                rb4[p] = *(const float4*)(XB + (size_t)ssrc[row] * XSTR + kg);   \
            } else {                                                             \
                int rg = row0 + row;                                             \
                ra[p] = (rg < M) ? *(const float4*)(A + (size_t)rg * KLEN + kg)  \
                                 : make_float4(0.f, 0.f, 0.f, 0.f);              \
            }                                                                    \
        }                                                                        \
    } while (0)

#define STS_A(c, buf)                                                            \
    do {                                                                         \
        int kg = (c) * 32 + sseg * 4;                                            \
        _Pragma("unroll")                                                        \
        for (int p = 0; p < PASSES; p++) {                                       \
            int row = p * 32 + srow;                                             \
            float4 v = ra[p];                                                    \
            if (GATHER) {                                                        \
                float4 vb = rb4[p];                                              \
                float4 vc = *(const float4*)(bpre + kg);                         \
                v.x = fmaxf(v.x + vb.x + vc.x, 0.f);                             \
                v.y = fmaxf(v.y + vb.y + vc.y, 0.f);                             \
                v.z = fmaxf(v.z + vb.z + vc.z, 0.f);                             \
                v.w = fmaxf(v.w + vb.w + vc.w, 0.f);                             \
            }                                                                    \
            float4 o;                                                            \
            o.x = __uint_as_float(f2tf32(v.x));                                  \
            o.y = __uint_as_float(f2tf32(v.y));                                  \
            o.z = __uint_as_float(f2tf32(v.z));                                  \
            o.w = __uint_as_float(f2tf32(v.w));                                  \
            *(float4*)(sA + (buf) * ASLOT_A + row * 36 + sseg * 4) = o;          \
        }                                                                        \
    } while (0)

    float acc[2][NT][4];
#pragma unroll
    for (int mt = 0; mt < 2; mt++)
#pragma unroll
        for (int nt = 0; nt < NT; nt++)
#pragma unroll
            for (int j = 0; j < 4; j++) acc[mt][nt][j] = 0.f;

    // prologue
    ISSUE_B(0, 0);
    LOAD_A(0);
    STS_A(0, 0);

#pragma unroll
    for (int c = 0; c < NCH; c++) {
        const int buf = c & 1;
        asm volatile("cp.async.wait_group 0;" ::: "memory");
        __syncthreads();
        if (c + 1 < NCH) {
            ISSUE_B(c + 1, buf ^ 1);
            LOAD_A(c + 1);
        }
        // mma over chunk c (ldmatrix fragment loads)
        const uint32_t aB = aLdm + (uint32_t)(buf * ASLOT_A * 4);
        const uint32_t bB = bLdm + (uint32_t)(buf * ASLOT_B * 4);
#pragma unroll
        for (int ks = 0; ks < 4; ks++) {
            uint32_t a0[4], a1[4];
            ldsm4(a0, aB + (uint32_t)ks * 32u);
            ldsm4(a1, aB + 16u * 144u + (uint32_t)ks * 32u);
#pragma unroll
            for (int ntp = 0; ntp < NT / 2; ntp++) {
                uint32_t b[4];
                ldsm4(b, bB + (uint32_t)ntp * 16u * 144u + (uint32_t)ks * 32u);
                mma8(acc[0][2 * ntp + 0], a0, b[0], b[1]);
                mma8(acc[1][2 * ntp + 0], a1, b[0], b[1]);
                mma8(acc[0][2 * ntp + 1], a0, b[2], b[3]);
                mma8(acc[1][2 * ntp + 1], a1, b[2], b[3]);
            }
        }
        if (c + 1 < NCH) STS_A(c + 1, buf ^ 1);
    }

    // ---- epilogue ----
#pragma unroll
    for (int mt = 0; mt < 2; mt++) {
#pragma unroll
        for (int part = 0; part < 2; part++) {
            const int rloc = wm * 32 + mt * 16 + lr + part * 8;
            const int rg = row0 + rloc;
            if (!(GATHER || SCATTER) && rg >= M) continue;
            float* outp = SCATTER ? (C + (size_t)sdst[rloc] * 256)
                                  : (C + (size_t)rg * CSTR);
#pragma unroll
            for (int nt = 0; nt < NT; nt++) {
                const int col = col0 + wn * WNW + nt * 8 + 2 * lc;
                float v0 = acc[mt][nt][part * 2 + 0];
                float v1 = acc[mt][nt][part * 2 + 1];
                if (ADD_BIAS) { v0 += bias[col]; v1 += bias[col + 1]; }
                if (RELU_OUT) { v0 = fmaxf(v0, 0.f); v1 = fmaxf(v1, 0.f); }
                if (SCATTER) {
                    red2(outp + col, v0, v1);
                } else {
                    *(float2*)(outp + col) = make_float2(v0, v1);
                }
            }
        }
    }
}

static constexpr size_t MM_SMEM128 = 2u * (128 * 36 + 128 * 36) * 4u + 1024u;  // 74752
static constexpr size_t MM_SMEM_E  = 2u * (64 * 36 + 256 * 36) * 4u + 1024u;   // 93184

// ---------------- relu + layernorm with deg*b3 pre-add ----------------
__global__ void relu_ln_kernel(const float* __restrict__ IN,
                               const float* __restrict__ degf, const float* __restrict__ b3,
                               const float* __restrict__ g, const float* __restrict__ b,
                               float* __restrict__ OUT)
{
    int gid = blockIdx.x * blockDim.x + threadIdx.x;
    int node = gid >> 5;
    int lane = gid & 31;
    if (node >= N_NODES) return;
    const float* x = &IN[(size_t)node * 256];
    float dg = degf[node];
    float v[8];
    float s = 0.f;
#pragma unroll
    for (int q = 0; q < 2; q++) {
        float4 t = *(const float4*)(&x[lane * 8 + q * 4]);
        float4 bb = *(const float4*)(&b3[lane * 8 + q * 4]);
        v[q * 4 + 0] = fmaxf(fmaf(dg, bb.x, t.x), 0.f);
        v[q * 4 + 1] = fmaxf(fmaf(dg, bb.y, t.y), 0.f);
        v[q * 4 + 2] = fmaxf(fmaf(dg, bb.z, t.z), 0.f);
        v[q * 4 + 3] = fmaxf(fmaf(dg, bb.w, t.w), 0.f);
    }
#pragma unroll
    for (int i = 0; i < 8; i++) s += v[i];
#pragma unroll
    for (int o = 16; o > 0; o >>= 1) s += __shfl_xor_sync(0xffffffffu, s, o);
    float mu = s * (1.f / 256.f);
    float vs = 0.f;
#pragma unroll
    for (int i = 0; i < 8; i++) { float d = v[i] - mu; vs += d * d; }
#pragma unroll
    for (int o = 16; o > 0; o >>= 1) vs += __shfl_xor_sync(0xffffffffu, vs, o);
    float inv = rsqrtf(vs * (1.f / 256.f) + 1e-5f);
#pragma unroll
    for (int i = 0; i < 8; i++) {
        int c = lane * 8 + i;
        OUT[(size_t)node * 256 + c] = (v[i] - mu) * inv * g[c] + b[c];
    }
}

// ---------------- logits = T1 @ aw2 + ab2 (N x 32) ----------------
__global__ void logits_kernel(const float* __restrict__ T1, const float* __restrict__ aw2,
                              const float* __restrict__ ab2, float* __restrict__ LG)
{
    int c = threadIdx.x;
    int n = blockIdx.x * blockDim.y + threadIdx.y;
    if (n >= N_NODES) return;
    const float* t = &T1[(size_t)n * 256];
    float acc = ab2[c];
#pragma unroll 8
    for (int k = 0; k < 256; k++) acc = fmaf(t[k], aw2[k * 32 + c], acc);
    LG[n * 32 + c] = acc;
}

// ---------------- gumbel softmax + loss partials ----------------
__global__ void gumbel_kernel(const float* __restrict__ LG, const float* __restrict__ U,
                              float* __restrict__ sOut, float* __restrict__ colsum,
                              float* __restrict__ entsum)
{
    int lane = threadIdx.x & 31;
    int gw = (blockIdx.x * blockDim.x + threadIdx.x) >> 5;
    int nw = (gridDim.x * blockDim.x) >> 5;
    float colAcc = 0.f, entAcc = 0.f;
    for (int n = gw; n < N_NODES; n += nw) {
        float u = U[n * 32 + lane];
        float gn = -logf(-logf(u + EPSF) + EPSF);
        float v = LG[n * 32 + lane] + gn;
        float mx = v;
#pragma unroll
        for (int o = 16; o > 0; o >>= 1) mx = fmaxf(mx, __shfl_xor_sync(0xffffffffu, mx, o));
        float e = expf(v - mx);
        float ssum = e;
#pragma unroll
        for (int o = 16; o > 0; o >>= 1) ssum += __shfl_xor_sync(0xffffffffu, ssum, o);
        float sv = e / ssum;
        sOut[n * 32 + lane] = sv;
        colAcc += sv;
        entAcc += sv * logf(sv + EPSF);
    }
    atomicAdd(&colsum[lane], colAcc);
#pragma unroll
    for (int o = 16; o > 0; o >>= 1) entAcc += __shfl_xor_sync(0xffffffffu, entAcc, o);
    if (lane == 0) atomicAdd(entsum, entAcc);
}

__global__ void loss_kernel(const float* __restrict__ colsum, const float* __restrict__ entsum,
                            float* __restrict__ outLoss)
{
    int lane = threadIdx.x;
    float avg = colsum[lane] * (1.f / (float)N_NODES);
    float dv = avg * logf(avg + EPSF);
#pragma unroll
    for (int o = 16; o > 0; o >>= 1) dv += __shfl_xor_sync(0xffffffffu, dv, o);
    if (lane == 0) outLoss[0] = dv - entsum[0] * (1.f / (float)N_NODES);
}

__global__ void bounds_kernel(const int* __restrict__ batch, int* __restrict__ bstart)
{
    int t = threadIdx.x;
    if (t > B_BATCH) return;
    int lo = 0, hi = N_NODES;
    while (lo < hi) {
        int mid = (lo + hi) >> 1;
        if (batch[mid] < t) lo = mid + 1; else hi = mid;
    }
    bstart[t] = lo;
}

__global__ void pooled_kernel(const float* __restrict__ X2, const float* __restrict__ S,
                              const int* __restrict__ bstart, float* __restrict__ pooled)
{
    int b = blockIdx.x;
    int nchunk = gridDim.y;
    int s0 = bstart[b], s1 = bstart[b + 1];
    int len = s1 - s0;
    int per = (len + nchunk - 1) / nchunk;
    int n0 = s0 + blockIdx.y * per;
    int n1 = min(n0 + per, s1);
    if (n0 >= n1) return;

    int h = threadIdx.x;
    float acc[32];
#pragma unroll
    for (int k = 0; k < 32; k++) acc[k] = 0.f;

    __shared__ float st[8][33];
    for (int basei = n0; basei < n1; basei += 8) {
        __syncthreads();
        {
            int rr = threadIdx.x >> 5, cc = threadIdx.x & 31;
            st[rr][cc] = (basei + rr < n1) ? S[(size_t)(basei + rr) * 32 + cc] : 0.f;
        }
        __syncthreads();
        int cnt = min(8, n1 - basei);
        for (int rr = 0; rr < cnt; rr++) {
            float xv = X2[(size_t)(basei + rr) * 256 + h];
#pragma unroll
            for (int k = 0; k < 32; k++) acc[k] = fmaf(st[rr][k], xv, acc[k]);
        }
    }
#pragma unroll
    for (int k = 0; k < 32; k++)
        atomicAdd(&pooled[((size_t)b * 32 + k) * 256 + h], acc[k]);
}

__global__ void out2_kernel(const float* __restrict__ TO, const float* __restrict__ ow2,
                            const float* __restrict__ ob2, float* __restrict__ out)
{
    int r = blockIdx.x;
    int c = threadIdx.x;
    const float* t = &TO[(size_t)r * 256];
    float acc = ob2[c];
#pragma unroll 8
    for (int k = 0; k < 256; k++) acc = fmaf(t[k], ow2[k * 128 + c], acc);
    out[(size_t)r * 128 + c] = acc;
}

// ===================== launch =====================
extern "C" void kernel_launch(void* const* d_in, const int* in_sizes, int n_in,
                              void* d_out, int out_size)
{
    const float* x    = (const float*)d_in[0];
    const float* u    = (const float*)d_in[1];
    const int*   ei   = (const int*)d_in[2];
    const int*   batch= (const int*)d_in[3];
    const float* g1w1 = (const float*)d_in[4];
    const float* g1b1 = (const float*)d_in[5];
    const float* g1w2 = (const float*)d_in[6];
    const float* g1b2 = (const float*)d_in[7];
    const float* g1w3 = (const float*)d_in[8];
    const float* g1b3 = (const float*)d_in[9];
    const float* ln1g = (const float*)d_in[10];
    const float* ln1b = (const float*)d_in[11];
    const float* g2w1 = (const float*)d_in[12];
    const float* g2b1 = (const float*)d_in[13];
    const float* g2w2 = (const float*)d_in[14];
    const float* g2b2 = (const float*)d_in[15];
    const float* g2w3 = (const float*)d_in[16];
    const float* g2b3 = (const float*)d_in[17];
    const float* ln2g = (const float*)d_in[18];
    const float* ln2b = (const float*)d_in[19];
    const float* aw1  = (const float*)d_in[20];
    const float* ab1  = (const float*)d_in[21];
    const float* aw2  = (const float*)d_in[22];
    const float* ab2  = (const float*)d_in[23];
    const float* ow1  = (const float*)d_in[24];
    const float* ob1  = (const float*)d_in[25];
    const float* ow2  = (const float*)d_in[26];
    const float* ob2  = (const float*)d_in[27];

    const int* srcI = ei;
    const int* dstI = ei + N_EDGES;

    float* out        = (float*)d_out;
    float* out_latent = out;
    float* out_s      = out + B_BATCH * S_DIM * L_DIM;
    float* out_loss   = out_s + (size_t)N_NODES * S_DIM;

    float *pXAB, *pHS1, *pHS2, *pACC, *pXLN, *pX2, *pT1, *pLG, *pDeg, *pPooled, *pTO, *pColsum, *pEntsum;
    float *pWT1, *pWT2, *pWT3, *pWT4, *pWT5, *pWT6, *pWTA, *pWTO;
    int* pBstart;
    cudaGetSymbolAddress((void**)&pXAB, d_XAB);
    cudaGetSymbolAddress((void**)&pHS1, d_HS1);
    cudaGetSymbolAddress((void**)&pHS2, d_HS2);
    cudaGetSymbolAddress((void**)&pACC, d_ACC);
    cudaGetSymbolAddress((void**)&pXLN, d_XLN);
    cudaGetSymbolAddress((void**)&pX2, d_X2);
    cudaGetSymbolAddress((void**)&pT1, d_T1);
    cudaGetSymbolAddress((void**)&pLG, d_LG);
    cudaGetSymbolAddress((void**)&pDeg, d_degf);
    cudaGetSymbolAddress((void**)&pPooled, d_pooled);
    cudaGetSymbolAddress((void**)&pTO, d_TO);
    cudaGetSymbolAddress((void**)&pColsum, d_colsum);
    cudaGetSymbolAddress((void**)&pEntsum, d_entsum);
    cudaGetSymbolAddress((void**)&pBstart, d_bstart);
    cudaGetSymbolAddress((void**)&pWT1, d_WT1);
    cudaGetSymbolAddress((void**)&pWT2, d_WT2);
    cudaGetSymbolAddress((void**)&pWT3, d_WT3);
    cudaGetSymbolAddress((void**)&pWT4, d_WT4);
    cudaGetSymbolAddress((void**)&pWT5, d_WT5);
    cudaGetSymbolAddress((void**)&pWT6, d_WT6);
    cudaGetSymbolAddress((void**)&pWTA, d_WTA);
    cudaGetSymbolAddress((void**)&pWTO, d_WTO);

    cudaFuncSetAttribute(mma_gemm<0,0,0,0,64,512,256,128,128>,  cudaFuncAttributeMaxDynamicSharedMemorySize, (int)MM_SMEM128);
    cudaFuncSetAttribute(mma_gemm<1,1,1,1,256,256,512,64,256>,  cudaFuncAttributeMaxDynamicSharedMemorySize, (int)MM_SMEM_E);
    cudaFuncSetAttribute(mma_gemm<0,0,0,0,256,256,256,128,128>, cudaFuncAttributeMaxDynamicSharedMemorySize, (int)MM_SMEM128);
    cudaFuncSetAttribute(mma_gemm<0,0,0,0,256,512,256,128,128>, cudaFuncAttributeMaxDynamicSharedMemorySize, (int)MM_SMEM128);
    cudaFuncSetAttribute(mma_gemm<0,0,1,1,256,256,256,128,128>, cudaFuncAttributeMaxDynamicSharedMemorySize, (int)MM_SMEM128);

    const dim3 GN((N_NODES + 127) / 128, 2);    // 157 x 2
    const dim3 GN4((N_NODES + 127) / 128, 4);   // 157 x 4 (XAB producer)
    const dim3 GE(N_EDGES / 64, 1);             // 5000 x 1 (M=64, N=256 edge tiles)

    // ---- fused zeroing + degree + all weight transposes ----
    {
        ZeroPars zp;
        zp.p[0] = pHS1;    zp.n[0] = N_NODES * H_DIM;
        zp.p[1] = pHS2;    zp.n[1] = N_NODES * H_DIM;
        zp.p[2] = pDeg;    zp.n[2] = N_NODES;
        zp.p[3] = pColsum; zp.n[3] = S_DIM;
        zp.p[4] = pEntsum; zp.n[4] = 1;
        zp.p[5] = pPooled; zp.n[5] = B_BATCH * S_DIM * H_DIM;
        zero_all<<<dim3(160, 6), 256>>>(zp);
    }
    deg_kernel<<<256, 256>>>(dstI, pDeg);
    {
        TransPars tp;
        tp.src[0] = g1w1;             tp.dst[0] = pWT1;            tp.R[0] = 64;
        tp.src[1] = g1w1 + 64 * 256;  tp.dst[1] = pWT1 + 256 * 64; tp.R[1] = 64;
        tp.src[2] = g1w2;             tp.dst[2] = pWT2;            tp.R[2] = 256;
        tp.src[3] = g1w3;             tp.dst[3] = pWT3;            tp.R[3] = 256;
        tp.src[4] = g2w1;             tp.dst[4] = pWT4;            tp.R[4] = 256;
        tp.src[5] = g2w1 + 256 * 256; tp.dst[5] = pWT4 + 256 * 256;tp.R[5] = 256;
        tp.src[6] = g2w2;             tp.dst[6] = pWT5;            tp.R[6] = 256;
        tp.src[7] = g2w3;             tp.dst[7] = pWT6;            tp.R[7] = 256;
        tp.src[8] = aw1;              tp.dst[8] = pWTA;            tp.R[8] = 256;
        tp.src[9] = ow1;              tp.dst[9] = pWTO;            tp.R[9] = 256;
        dim3 tg(8, 8, 10), tb(32, 8);
        transpose_all<<<tg, tb>>>(tp);
    }

    // ---- layer 1 ----
    mma_gemm<0,0,0,0,64,512,256,128,128><<<GN4, 256, MM_SMEM128>>>(
        x, N_NODES, nullptr, nullptr, nullptr, nullptr, nullptr, pWT1, nullptr, pXAB);
    mma_gemm<1,1,1,1,256,256,512,64,256><<<GE, 256, MM_SMEM_E>>>(
        nullptr, N_EDGES, pXAB, pXAB + 256, g1b1, srcI, dstI, pWT2, g1b2, pHS1);
    mma_gemm<0,0,0,0,256,256,256,128,128><<<GN, 256, MM_SMEM128>>>(
        pHS1, N_NODES, nullptr, nullptr, nullptr, nullptr, nullptr, pWT3, nullptr, pACC);
    relu_ln_kernel<<<(N_NODES * 32 + 255) / 256, 256>>>(pACC, pDeg, g1b3, ln1g, ln1b, pXLN);

    // ---- layer 2 ----
    mma_gemm<0,0,0,0,256,512,256,128,128><<<GN4, 256, MM_SMEM128>>>(
        pXLN, N_NODES, nullptr, nullptr, nullptr, nullptr, nullptr, pWT4, nullptr, pXAB);
    mma_gemm<1,1,1,1,256,256,512,64,256><<<GE, 256, MM_SMEM_E>>>(
        nullptr, N_EDGES, pXAB, pXAB + 256, g2b1, srcI, dstI, pWT5, g2b2, pHS2);
    mma_gemm<0,0,0,0,256,256,256,128,128><<<GN, 256, MM_SMEM128>>>(
        pHS2, N_NODES, nullptr, nullptr, nullptr, nullptr, nullptr, pWT6, nullptr, pACC);
    relu_ln_kernel<<<(N_NODES * 32 + 255) / 256, 256>>>(pACC, pDeg, g2b3, ln2g, ln2b, pX2);

    // ---- assignment ----
    mma_gemm<0,0,1,1,256,256,256,128,128><<<GN, 256, MM_SMEM128>>>(
        pX2, N_NODES, nullptr, nullptr, nullptr, nullptr, nullptr, pWTA, ab1, pT1);
    {
        dim3 lb(32, 8);
        logits_kernel<<<(N_NODES + 7) / 8, lb>>>(pT1, aw2, ab2, pLG);
    }
    gumbel_kernel<<<80, 256>>>(pLG, u, out_s, pColsum, pEntsum);
    loss_kernel<<<1, 32>>>(pColsum, pEntsum, out_loss);

    // ---- pooling ----
    bounds_kernel<<<1, 32>>>(batch, pBstart);
    {
        dim3 pg(B_BATCH, 8);
        pooled_kernel<<<pg, 256>>>(pX2, out_s, pBstart, pPooled);
    }

    // ---- output MLP ----
    mma_gemm<0,0,1,1,256,256,256,128,128><<<dim3(4, 2), 256, MM_SMEM128>>>(
        pPooled, B_BATCH * S_DIM, nullptr, nullptr, nullptr,
        nullptr, nullptr, pWTO, ob1, pTO);
    out2_kernel<<<B_BATCH * S_DIM, 128>>>(pTO, ow2, ob2, out_latent);
}

// round 16
// speedup vs baseline: 1.5257x; 1.5257x over previous
#include <cuda_runtime.h>
#include <cstdint>

// Problem constants
#define N_NODES 20000
#define N_EDGES 320000
#define F_IN    64
#define H_DIM   256
#define S_DIM   32
#define L_DIM   128
#define B_BATCH 16
#define EPSF    1e-9f

// ===================== helpers =====================
__device__ __forceinline__ uint32_t smem_u32(const void* p) {
    uint32_t a;
    asm("{ .reg .u64 t; cvta.to.shared.u64 t, %1; cvt.u32.u64 %0, t; }" : "=r"(a) : "l"(p));
    return a;
}
__device__ __forceinline__ uint32_t f2tf32(float f) {
    uint32_t r;
    asm("cvt.rna.tf32.f32 %0, %1;" : "=r"(r) : "f"(f));
    return r;
}
__device__ __forceinline__ void mma8(float* c, const uint32_t* a, uint32_t b0, uint32_t b1) {
    asm volatile(
        "mma.sync.aligned.m16n8k8.row.col.f32.tf32.tf32.f32 "
        "{%0,%1,%2,%3}, {%4,%5,%6,%7}, {%8,%9}, {%0,%1,%2,%3};"
        : "+f"(c[0]), "+f"(c[1]), "+f"(c[2]), "+f"(c[3])
        : "r"(a[0]), "r"(a[1]), "r"(a[2]), "r"(a[3]), "r"(b0), "r"(b1));
}
__device__ __forceinline__ void ldsm4(uint32_t* r, uint32_t addr) {
    asm volatile("ldmatrix.sync.aligned.m8n8.x4.shared.b16 {%0,%1,%2,%3}, [%4];"
                 : "=r"(r[0]), "=r"(r[1]), "=r"(r[2]), "=r"(r[3]) : "r"(addr));
}
__device__ __forceinline__ void red2(float* addr, float v0, float v1) {
    asm volatile("red.global.add.v2.f32 [%0], {%1, %2};"
                 :: "l"(addr), "f"(v0), "f"(v1) : "memory");
}

// ===================== device scratch =====================
__device__ float d_XAB[(size_t)N_NODES * 512];   // [n][0:256]=XA, [256:512]=XB
__device__ float d_HS1[N_NODES * H_DIM];
__device__ float d_HS2[N_NODES * H_DIM];
__device__ float d_ACC[N_NODES * H_DIM];
__device__ float d_XLN[N_NODES * H_DIM];
__device__ float d_X2[N_NODES * H_DIM];
__device__ float d_T1[N_NODES * H_DIM];
__device__ float d_LG[N_NODES * S_DIM];
__device__ float d_degf[N_NODES];
__device__ float d_pooled[B_BATCH * S_DIM * H_DIM];
__device__ float d_TO[B_BATCH * S_DIM * H_DIM];
__device__ float d_colsum[S_DIM];
__device__ float d_entsum[1];
__device__ int   d_bstart[B_BATCH + 1];
// transposed (tf32-rounded) weights [outN][K]
__device__ float d_WT1[512 * 64];     // layer-1 w1 (both halves)
__device__ float d_WT2[256 * 256];
__device__ float d_WT3[256 * 256];
__device__ float d_WT4[512 * 256];    // layer-2 w1 (both halves)
__device__ float d_WT5[256 * 256];
__device__ float d_WT6[256 * 256];
__device__ float d_WTA[256 * 256];
__device__ float d_WTO[256 * 256];

// ===================== fused zero =====================
struct ZeroPars { float* p[6]; int n[6]; };
__global__ void zero_all(ZeroPars zp) {
    int r = blockIdx.y;
    float* p = zp.p[r];
    int n = zp.n[r];
    int i = blockIdx.x * blockDim.x + threadIdx.x;
    int st = gridDim.x * blockDim.x;
    for (; i < n; i += st) p[i] = 0.f;
}

__global__ void deg_kernel(const int* __restrict__ dst, float* __restrict__ degf) {
    int i = blockIdx.x * blockDim.x + threadIdx.x;
    int st = gridDim.x * blockDim.x;
    for (; i < N_EDGES; i += st) atomicAdd(&degf[dst[i]], 1.f);
}

// ===================== batched transpose (tf32 round) =====================
struct TransPars { const float* src[10]; float* dst[10]; int R[10]; };
__global__ void transpose_all(TransPars tp) {
    __shared__ float t[32][33];
    int m = blockIdx.z;
    const float* in = tp.src[m];
    float* out = tp.dst[m];
    int R = tp.R[m];
    int c0 = blockIdx.x * 32, r0 = blockIdx.y * 32;
    if (r0 >= R) return;
    for (int j = threadIdx.y; j < 32; j += 8) {
        int r = r0 + j, c = c0 + threadIdx.x;
        t[j][threadIdx.x] = (r < R) ? in[(size_t)r * 256 + c] : 0.f;
    }
    __syncthreads();
    for (int j = threadIdx.y; j < 32; j += 8) {
        int oc = c0 + j, orr = r0 + threadIdx.x;
        if (orr < R)
            out[(size_t)oc * R + orr] = __uint_as_float(f2tf32(t[threadIdx.x][j]));
    }
}

// ===================== tf32 mma.sync GEMM (2-stage, R9 schedule) ==============
// CTA tile MTILE(M) x NTILE(N), grid.y picks the NTILE-col block. K chunks of 32.
// 8 warps: WM_CNT = MTILE/32 M-warps x (8/WM_CNT) N-warps, warp n-width WNW.
// GATHER: A row = relu(XA[gdst*XSTR] + XB[gsrc*XSTR] + bpre).
// SCATTER: epilogue red.v2 into C[gdst].
// Smem stride 36 floats: conflict-free ldmatrix.
// A staging: 8 threads/row x 16B each, MTILE/32 passes (full 128B wavefronts).
template<int GATHER, int SCATTER, int RELU_OUT, int ADD_BIAS, int KLEN,
         int CSTR = 256, int XSTR = 256, int MTILE = 128, int NTILE = 128>
__global__ void __launch_bounds__(256, 2) mma_gemm(
    const float* __restrict__ A, int M,
    const float* __restrict__ XA, const float* __restrict__ XB,
    const float* __restrict__ bpre,
    const int* __restrict__ gsrc, const int* __restrict__ gdst,
    const float* __restrict__ WT,   // [outN][KLEN] K-major, tf32-rounded
    const float* __restrict__ bias,
    float* __restrict__ C)
{
    constexpr int WM_CNT  = MTILE / 32;         // 4 or 2
    constexpr int WN_CNT  = 8 / WM_CNT;         // 2 or 4
    constexpr int WNW     = NTILE / WN_CNT;     // warp n-width (64 here)
    constexpr int NT      = WNW / 8;            // 8
    constexpr int PASSES  = MTILE / 32;         // A staging passes (8 thr/row)
    constexpr int BROWS   = NTILE / 128;        // B row-groups per thread: 1 or 2
    constexpr int ASLOT_A = MTILE * 36;
    constexpr int ASLOT_B = NTILE * 36;

    extern __shared__ float sm[];
    float* sA = sm;                           // 2 * ASLOT_A
    float* sB = sm + 2 * ASLOT_A;             // 2 * ASLOT_B
    int* sdst = (int*)(sm + 2 * ASLOT_A + 2 * ASLOT_B);
    int* ssrc = sdst + MTILE;

    const int tid  = threadIdx.x;
    const int lane = tid & 31;
    const int wid  = tid >> 5;
    const int wm = wid % WM_CNT;
    const int wn = wid / WM_CNT;
    const int lr = lane >> 2;
    const int lc = lane & 3;
    const int row0 = blockIdx.x * MTILE;
    const int col0 = blockIdx.y * NTILE;
    constexpr int NCH = KLEN / 32;

    if ((GATHER || SCATTER) && tid < MTILE) {
        sdst[tid] = gdst[row0 + tid];
        if (GATHER) ssrc[tid] = gsrc[row0 + tid];
    }
    if (GATHER || SCATTER) __syncthreads();

    // A staging mapping: 8 threads per row, 16B (4 floats) per thread.
    const int srow = tid >> 3;    // 0..31 (row within pass)
    const int sseg = tid & 7;     // 0..7 (16B segment within 128B chunk-row)
    const int bn   = tid >> 1;
    const int bkh  = (tid & 1) << 4;
    const uint32_t sA_addr = smem_u32(sA);
    const uint32_t sB_addr = smem_u32(sB);
    const float* WTb = WT + (size_t)(col0 + bn) * KLEN + bkh;

    // ldmatrix per-thread base byte offsets (group = lane>>3, rif = lane&7)
    const int grp = lane >> 3;
    const int rif = lane & 7;
    const uint32_t aLdm = sA_addr
        + (uint32_t)(wm * 32 + (grp & 1) * 8 + rif) * 144u + (uint32_t)(grp >> 1) * 16u;
    const uint32_t bLdm = sB_addr
        + (uint32_t)(wn * WNW + (grp >> 1) * 8 + rif) * 144u + (uint32_t)(grp & 1) * 16u;

    float4 ra[PASSES], rb4[PASSES];

#define ISSUE_B(c, buf)                                                          \
    do {                                                                         \
        _Pragma("unroll")                                                        \
        for (int rr = 0; rr < BROWS; rr++) {                                     \
            uint32_t dstb = sB_addr                                              \
                + (uint32_t)((buf) * ASLOT_B + (bn + rr * 128) * 36 + bkh) * 4u; \
            const float* srcb = WTb + (size_t)rr * 128 * KLEN + (c) * 32;        \
            _Pragma("unroll")                                                    \
            for (int i = 0; i < 4; i++)                                          \
                asm volatile("cp.async.cg.shared.global [%0], [%1], 16;" ::      \
                             "r"(dstb + (uint32_t)i * 16u), "l"(srcb + i * 4) : "memory"); \
        }                                                                        \
        asm volatile("cp.async.commit_group;" ::: "memory");                     \
    } while (0)

#define LOAD_A(c)                                                                \
    do {                                                                         \
        int kg = (c) * 32 + sseg * 4;                                            \
        _Pragma("unroll")                                                        \
        for (int p = 0; p < PASSES; p++) {                                       \
            int row = p * 32 + srow;                                             \
            if (GATHER) {                                                        \
                ra[p]  = *(const float4*)(XA + (size_t)sdst[row] * XSTR + kg);   \
                rb4[p] = *(const float4*)(XB + (size_t)ssrc[row] * XSTR + kg);   \
            } else {                                                             \
                int rg = row0 + row;                                             \
                ra[p] = (rg < M) ? *(const float4*)(A + (size_t)rg * KLEN + kg)  \
                                 : make_float4(0.f, 0.f, 0.f, 0.f);              \
            }                                                                    \
        }                                                                        \
    } while (0)

#define STS_A(c, buf)                                                            \
    do {                                                                         \
        int kg = (c) * 32 + sseg * 4;                                            \
        _Pragma("unroll")                                                        \
        for (int p = 0; p < PASSES; p++) {                                       \
            int row = p * 32 + srow;                                             \
            float4 v = ra[p];                                                    \
            if (GATHER) {                                                        \
                float4 vb = rb4[p];                                              \
                float4 vc = *(const float4*)(bpre + kg);                         \
                v.x = fmaxf(v.x + vb.x + vc.x, 0.f);                             \
                v.y = fmaxf(v.y + vb.y + vc.y, 0.f);                             \
                v.z = fmaxf(v.z + vb.z + vc.z, 0.f);                             \
                v.w = fmaxf(v.w + vb.w + vc.w, 0.f);                             \
            }                                                                    \
            float4 o;                                                            \
            o.x = __uint_as_float(f2tf32(v.x));                                  \
            o.y = __uint_as_float(f2tf32(v.y));                                  \
            o.z = __uint_as_float(f2tf32(v.z));                                  \
            o.w = __uint_as_float(f2tf32(v.w));                                  \
            *(float4*)(sA + (buf) * ASLOT_A + row * 36 + sseg * 4) = o;          \
        }                                                                        \
    } while (0)

    float acc[2][NT][4];
#pragma unroll
    for (int mt = 0; mt < 2; mt++)
#pragma unroll
        for (int nt = 0; nt < NT; nt++)
#pragma unroll
            for (int j = 0; j < 4; j++) acc[mt][nt][j] = 0.f;

    // prologue
    ISSUE_B(0, 0);
    LOAD_A(0);
    STS_A(0, 0);

#pragma unroll
    for (int c = 0; c < NCH; c++) {
        const int buf = c & 1;
        asm volatile("cp.async.wait_group 0;" ::: "memory");
        __syncthreads();
        if (c + 1 < NCH) {
            ISSUE_B(c + 1, buf ^ 1);
            LOAD_A(c + 1);
        }
        // mma over chunk c (ldmatrix fragment loads)
        const uint32_t aB = aLdm + (uint32_t)(buf * ASLOT_A * 4);
        const uint32_t bB = bLdm + (uint32_t)(buf * ASLOT_B * 4);
#pragma unroll
        for (int ks = 0; ks < 4; ks++) {
            uint32_t a0[4], a1[4];
            ldsm4(a0, aB + (uint32_t)ks * 32u);
            ldsm4(a1, aB + 16u * 144u + (uint32_t)ks * 32u);
#pragma unroll
            for (int ntp = 0; ntp < NT / 2; ntp++) {
                uint32_t b[4];
                ldsm4(b, bB + (uint32_t)ntp * 16u * 144u + (uint32_t)ks * 32u);
                mma8(acc[0][2 * ntp + 0], a0, b[0], b[1]);
                mma8(acc[1][2 * ntp + 0], a1, b[0], b[1]);
                mma8(acc[0][2 * ntp + 1], a0, b[2], b[3]);
                mma8(acc[1][2 * ntp + 1], a1, b[2], b[3]);
            }
        }
        if (c + 1 < NCH) STS_A(c + 1, buf ^ 1);
    }

    // ---- epilogue ----
#pragma unroll
    for (int mt = 0; mt < 2; mt++) {
#pragma unroll
        for (int part = 0; part < 2; part++) {
            const int rloc = wm * 32 + mt * 16 + lr + part * 8;
            const int rg = row0 + rloc;
            if (!(GATHER || SCATTER) && rg >= M) continue;
            float* outp = SCATTER ? (C + (size_t)sdst[rloc] * 256)
                                  : (C + (size_t)rg * CSTR);
#pragma unroll
            for (int nt = 0; nt < NT; nt++) {
                const int col = col0 + wn * WNW + nt * 8 + 2 * lc;
                float v0 = acc[mt][nt][part * 2 + 0];
                float v1 = acc[mt][nt][part * 2 + 1];
                if (ADD_BIAS) { v0 += bias[col]; v1 += bias[col + 1]; }
                if (RELU_OUT) { v0 = fmaxf(v0, 0.f); v1 = fmaxf(v1, 0.f); }
                if (SCATTER) {
                    red2(outp + col, v0, v1);
                } else {
                    *(float2*)(outp + col) = make_float2(v0, v1);
                }
            }
        }
    }
}

static constexpr size_t MM_SMEM128 = 2u * (128 * 36 + 128 * 36) * 4u + 1024u;  // 74752
static constexpr size_t MM_SMEM_E  = 2u * (64 * 36 + 256 * 36) * 4u + 1024u;   // 93184

// ---------------- relu + layernorm with deg*b3 pre-add ----------------
__global__ void relu_ln_kernel(const float* __restrict__ IN,
                               const float* __restrict__ degf, const float* __restrict__ b3,
                               const float* __restrict__ g, const float* __restrict__ b,
                               float* __restrict__ OUT)
{
    int gid = blockIdx.x * blockDim.x + threadIdx.x;
    int node = gid >> 5;
    int lane = gid & 31;
    if (node >= N_NODES) return;
    const float* x = &IN[(size_t)node * 256];
    float dg = degf[node];
    float v[8];
    float s = 0.f;
#pragma unroll
    for (int q = 0; q < 2; q++) {
        float4 t = *(const float4*)(&x[lane * 8 + q * 4]);
        float4 bb = *(const float4*)(&b3[lane * 8 + q * 4]);
        v[q * 4 + 0] = fmaxf(fmaf(dg, bb.x, t.x), 0.f);
        v[q * 4 + 1] = fmaxf(fmaf(dg, bb.y, t.y), 0.f);
        v[q * 4 + 2] = fmaxf(fmaf(dg, bb.z, t.z), 0.f);
        v[q * 4 + 3] = fmaxf(fmaf(dg, bb.w, t.w), 0.f);
    }
#pragma unroll
    for (int i = 0; i < 8; i++) s += v[i];
#pragma unroll
    for (int o = 16; o > 0; o >>= 1) s += __shfl_xor_sync(0xffffffffu, s, o);
    float mu = s * (1.f / 256.f);
    float vs = 0.f;
#pragma unroll
    for (int i = 0; i < 8; i++) { float d = v[i] - mu; vs += d * d; }
#pragma unroll
    for (int o = 16; o > 0; o >>= 1) vs += __shfl_xor_sync(0xffffffffu, vs, o);
    float inv = rsqrtf(vs * (1.f / 256.f) + 1e-5f);
#pragma unroll
    for (int i = 0; i < 8; i++) {
        int c = lane * 8 + i;
        OUT[(size_t)node * 256 + c] = (v[i] - mu) * inv * g[c] + b[c];
    }
}

// ---------------- logits = T1 @ aw2 + ab2 (N x 32) ----------------
__global__ void logits_kernel(const float* __restrict__ T1, const float* __restrict__ aw2,
                              const float* __restrict__ ab2, float* __restrict__ LG)
{
    int c = threadIdx.x;
    int n = blockIdx.x * blockDim.y + threadIdx.y;
    if (n >= N_NODES) return;
    const float* t = &T1[(size_t)n * 256];
    float acc = ab2[c];
#pragma unroll 8
    for (int k = 0; k < 256; k++) acc = fmaf(t[k], aw2[k * 32 + c], acc);
    LG[n * 32 + c] = acc;
}

// ---------------- gumbel softmax + loss partials ----------------
__global__ void gumbel_kernel(const float* __restrict__ LG, const float* __restrict__ U,
                              float* __restrict__ sOut, float* __restrict__ colsum,
                              float* __restrict__ entsum)
{
    int lane = threadIdx.x & 31;
    int gw = (blockIdx.x * blockDim.x + threadIdx.x) >> 5;
    int nw = (gridDim.x * blockDim.x) >> 5;
    float colAcc = 0.f, entAcc = 0.f;
    for (int n = gw; n < N_NODES; n += nw) {
        float u = U[n * 32 + lane];
        float gn = -logf(-logf(u + EPSF) + EPSF);
        float v = LG[n * 32 + lane] + gn;
        float mx = v;
#pragma unroll
        for (int o = 16; o > 0; o >>= 1) mx = fmaxf(mx, __shfl_xor_sync(0xffffffffu, mx, o));
        float e = expf(v - mx);
        float ssum = e;
#pragma unroll
        for (int o = 16; o > 0; o >>= 1) ssum += __shfl_xor_sync(0xffffffffu, ssum, o);
        float sv = e / ssum;
        sOut[n * 32 + lane] = sv;
        colAcc += sv;
        entAcc += sv * logf(sv + EPSF);
    }
    atomicAdd(&colsum[lane], colAcc);
#pragma unroll
    for (int o = 16; o > 0; o >>= 1) entAcc += __shfl_xor_sync(0xffffffffu, entAcc, o);
    if (lane == 0) atomicAdd(entsum, entAcc);
}

__global__ void loss_kernel(const float* __restrict__ colsum, const float* __restrict__ entsum,
                            float* __restrict__ outLoss)
{
    int lane = threadIdx.x;
    float avg = colsum[lane] * (1.f / (float)N_NODES);
    float dv = avg * logf(avg + EPSF);
#pragma unroll
    for (int o = 16; o > 0; o >>= 1) dv += __shfl_xor_sync(0xffffffffu, dv, o);
    if (lane == 0) outLoss[0] = dv - entsum[0] * (1.f / (float)N_NODES);
}

__global__ void bounds_kernel(const int* __restrict__ batch, int* __restrict__ bstart)
{
    int t = threadIdx.x;
    if (t > B_BATCH) return;
    int lo = 0, hi = N_NODES;
    while (lo < hi) {
        int mid = (lo + hi) >> 1;
        if (batch[mid] < t) lo = mid + 1; else hi = mid;
    }
    bstart[t] = lo;
}

__global__ void pooled_kernel(const float* __restrict__ X2, const float* __restrict__ S,
                              const int* __restrict__ bstart, float* __restrict__ pooled)
{
    int b = blockIdx.x;
    int nchunk = gridDim.y;
    int s0 = bstart[b], s1 = bstart[b + 1];
    int len = s1 - s0;
    int per = (len + nchunk - 1) / nchunk;
    int n0 = s0 + blockIdx.y * per;
    int n1 = min(n0 + per, s1);
    if (n0 >= n1) return;

    int h = threadIdx.x;
    float acc[32];
#pragma unroll
    for (int k = 0; k < 32; k++) acc[k] = 0.f;

    __shared__ float st[8][33];
    for (int basei = n0; basei < n1; basei += 8) {
        __syncthreads();
        {
            int rr = threadIdx.x >> 5, cc = threadIdx.x & 31;
            st[rr][cc] = (basei + rr < n1) ? S[(size_t)(basei + rr) * 32 + cc] : 0.f;
        }
        __syncthreads();
        int cnt = min(8, n1 - basei);
        for (int rr = 0; rr < cnt; rr++) {
            float xv = X2[(size_t)(basei + rr) * 256 + h];
#pragma unroll
            for (int k = 0; k < 32; k++) acc[k] = fmaf(st[rr][k], xv, acc[k]);
        }
    }
#pragma unroll
    for (int k = 0; k < 32; k++)
        atomicAdd(&pooled[((size_t)b * 32 + k) * 256 + h], acc[k]);
}

__global__ void out2_kernel(const float* __restrict__ TO, const float* __restrict__ ow2,
                            const float* __restrict__ ob2, float* __restrict__ out)
{
    int r = blockIdx.x;
    int c = threadIdx.x;
    const float* t = &TO[(size_t)r * 256];
    float acc = ob2[c];
#pragma unroll 8
    for (int k = 0; k < 256; k++) acc = fmaf(t[k], ow2[k * 128 + c], acc);
    out[(size_t)r * 128 + c] = acc;
}

// ===================== launch =====================
extern "C" void kernel_launch(void* const* d_in, const int* in_sizes, int n_in,
                              void* d_out, int out_size)
{
    const float* x    = (const float*)d_in[0];
    const float* u    = (const float*)d_in[1];
    const int*   ei   = (const int*)d_in[2];
    const int*   batch= (const int*)d_in[3];
    const float* g1w1 = (const float*)d_in[4];
    const float* g1b1 = (const float*)d_in[5];
    const float* g1w2 = (const float*)d_in[6];
    const float* g1b2 = (const float*)d_in[7];
    const float* g1w3 = (const float*)d_in[8];
    const float* g1b3 = (const float*)d_in[9];
    const float* ln1g = (const float*)d_in[10];
    const float* ln1b = (const float*)d_in[11];
    const float* g2w1 = (const float*)d_in[12];
    const float* g2b1 = (const float*)d_in[13];
    const float* g2w2 = (const float*)d_in[14];
    const float* g2b2 = (const float*)d_in[15];
    const float* g2w3 = (const float*)d_in[16];
    const float* g2b3 = (const float*)d_in[17];
    const float* ln2g = (const float*)d_in[18];
    const float* ln2b = (const float*)d_in[19];
    const float* aw1  = (const float*)d_in[20];
    const float* ab1  = (const float*)d_in[21];
    const float* aw2  = (const float*)d_in[22];
    const float* ab2  = (const float*)d_in[23];
    const float* ow1  = (const float*)d_in[24];
    const float* ob1  = (const float*)d_in[25];
    const float* ow2  = (const float*)d_in[26];
    const float* ob2  = (const float*)d_in[27];

    const int* srcI = ei;
    const int* dstI = ei + N_EDGES;

    float* out        = (float*)d_out;
    float* out_latent = out;
    float* out_s      = out + B_BATCH * S_DIM * L_DIM;
    float* out_loss   = out_s + (size_t)N_NODES * S_DIM;

    float *pXAB, *pHS1, *pHS2, *pACC, *pXLN, *pX2, *pT1, *pLG, *pDeg, *pPooled, *pTO, *pColsum, *pEntsum;
    float *pWT1, *pWT2, *pWT3, *pWT4, *pWT5, *pWT6, *pWTA, *pWTO;
    int* pBstart;
    cudaGetSymbolAddress((void**)&pXAB, d_XAB);
    cudaGetSymbolAddress((void**)&pHS1, d_HS1);
    cudaGetSymbolAddress((void**)&pHS2, d_HS2);
    cudaGetSymbolAddress((void**)&pACC, d_ACC);
    cudaGetSymbolAddress((void**)&pXLN, d_XLN);
    cudaGetSymbolAddress((void**)&pX2, d_X2);
    cudaGetSymbolAddress((void**)&pT1, d_T1);
    cudaGetSymbolAddress((void**)&pLG, d_LG);
    cudaGetSymbolAddress((void**)&pDeg, d_degf);
    cudaGetSymbolAddress((void**)&pPooled, d_pooled);
    cudaGetSymbolAddress((void**)&pTO, d_TO);
    cudaGetSymbolAddress((void**)&pColsum, d_colsum);
    cudaGetSymbolAddress((void**)&pEntsum, d_entsum);
    cudaGetSymbolAddress((void**)&pBstart, d_bstart);
    cudaGetSymbolAddress((void**)&pWT1, d_WT1);
    cudaGetSymbolAddress((void**)&pWT2, d_WT2);
    cudaGetSymbolAddress((void**)&pWT3, d_WT3);
    cudaGetSymbolAddress((void**)&pWT4, d_WT4);
    cudaGetSymbolAddress((void**)&pWT5, d_WT5);
    cudaGetSymbolAddress((void**)&pWT6, d_WT6);
    cudaGetSymbolAddress((void**)&pWTA, d_WTA);
    cudaGetSymbolAddress((void**)&pWTO, d_WTO);

    cudaFuncSetAttribute(mma_gemm<0,0,0,0,64,512,256,128,128>,  cudaFuncAttributeMaxDynamicSharedMemorySize, (int)MM_SMEM128);
    cudaFuncSetAttribute(mma_gemm<1,1,1,1,256,256,512,64,256>,  cudaFuncAttributeMaxDynamicSharedMemorySize, (int)MM_SMEM_E);
    cudaFuncSetAttribute(mma_gemm<0,0,0,0,256,256,256,128,128>, cudaFuncAttributeMaxDynamicSharedMemorySize, (int)MM_SMEM128);
    cudaFuncSetAttribute(mma_gemm<0,0,0,0,256,512,256,128,128>, cudaFuncAttributeMaxDynamicSharedMemorySize, (int)MM_SMEM128);
    cudaFuncSetAttribute(mma_gemm<0,0,1,1,256,256,256,128,128>, cudaFuncAttributeMaxDynamicSharedMemorySize, (int)MM_SMEM128);

    const dim3 GN((N_NODES + 127) / 128, 2);    // 157 x 2
    const dim3 GN4((N_NODES + 127) / 128, 4);   // 157 x 4 (XAB producer)
    const dim3 GE(N_EDGES / 64, 1);             // 5000 x 1 (M=64, N=256 edge tiles)

    // ---- fused zeroing + degree + all weight transposes ----
    {
        ZeroPars zp;
        zp.p[0] = pHS1;    zp.n[0] = N_NODES * H_DIM;
        zp.p[1] = pHS2;    zp.n[1] = N_NODES * H_DIM;
        zp.p[2] = pDeg;    zp.n[2] = N_NODES;
        zp.p[3] = pColsum; zp.n[3] = S_DIM;
        zp.p[4] = pEntsum; zp.n[4] = 1;
        zp.p[5] = pPooled; zp.n[5] = B_BATCH * S_DIM * H_DIM;
        zero_all<<<dim3(160, 6), 256>>>(zp);
    }
    deg_kernel<<<256, 256>>>(dstI, pDeg);
    {
        TransPars tp;
        tp.src[0] = g1w1;             tp.dst[0] = pWT1;            tp.R[0] = 64;
        tp.src[1] = g1w1 + 64 * 256;  tp.dst[1] = pWT1 + 256 * 64; tp.R[1] = 64;
        tp.src[2] = g1w2;             tp.dst[2] = pWT2;            tp.R[2] = 256;
        tp.src[3] = g1w3;             tp.dst[3] = pWT3;            tp.R[3] = 256;
        tp.src[4] = g2w1;             tp.dst[4] = pWT4;            tp.R[4] = 256;
        tp.src[5] = g2w1 + 256 * 256; tp.dst[5] = pWT4 + 256 * 256;tp.R[5] = 256;
        tp.src[6] = g2w2;             tp.dst[6] = pWT5;            tp.R[6] = 256;
        tp.src[7] = g2w3;             tp.dst[7] = pWT6;            tp.R[7] = 256;
        tp.src[8] = aw1;              tp.dst[8] = pWTA;            tp.R[8] = 256;
        tp.src[9] = ow1;              tp.dst[9] = pWTO;            tp.R[9] = 256;
        dim3 tg(8, 8, 10), tb(32, 8);
        transpose_all<<<tg, tb>>>(tp);
    }

    // ---- layer 1 ----
    mma_gemm<0,0,0,0,64,512,256,128,128><<<GN4, 256, MM_SMEM128>>>(
        x, N_NODES, nullptr, nullptr, nullptr, nullptr, nullptr, pWT1, nullptr, pXAB);
    mma_gemm<1,1,1,1,256,256,512,64,256><<<GE, 256, MM_SMEM_E>>>(
        nullptr, N_EDGES, pXAB, pXAB + 256, g1b1, srcI, dstI, pWT2, g1b2, pHS1);
    mma_gemm<0,0,0,0,256,256,256,128,128><<<GN, 256, MM_SMEM128>>>(
        pHS1, N_NODES, nullptr, nullptr, nullptr, nullptr, nullptr, pWT3, nullptr, pACC);
    relu_ln_kernel<<<(N_NODES * 32 + 255) / 256, 256>>>(pACC, pDeg, g1b3, ln1g, ln1b, pXLN);

    // ---- layer 2 ----
    mma_gemm<0,0,0,0,256,512,256,128,128><<<GN4, 256, MM_SMEM128>>>(
        pXLN, N_NODES, nullptr, nullptr, nullptr, nullptr, nullptr, pWT4, nullptr, pXAB);
    mma_gemm<1,1,1,1,256,256,512,64,256><<<GE, 256, MM_SMEM_E>>>(
        nullptr, N_EDGES, pXAB, pXAB + 256, g2b1, srcI, dstI, pWT5, g2b2, pHS2);
    mma_gemm<0,0,0,0,256,256,256,128,128><<<GN, 256, MM_SMEM128>>>(
        pHS2, N_NODES, nullptr, nullptr, nullptr, nullptr, nullptr, pWT6, nullptr, pACC);
    relu_ln_kernel<<<(N_NODES * 32 + 255) / 256, 256>>>(pACC, pDeg, g2b3, ln2g, ln2b, pX2);

    // ---- assignment ----
    mma_gemm<0,0,1,1,256,256,256,128,128><<<GN, 256, MM_SMEM128>>>(
        pX2, N_NODES, nullptr, nullptr, nullptr, nullptr, nullptr, pWTA, ab1, pT1);
    {
        dim3 lb(32, 8);
        logits_kernel<<<(N_NODES + 7) / 8, lb>>>(pT1, aw2, ab2, pLG);
    }
    gumbel_kernel<<<80, 256>>>(pLG, u, out_s, pColsum, pEntsum);
    loss_kernel<<<1, 32>>>(pColsum, pEntsum, out_loss);

    // ---- pooling ----
    bounds_kernel<<<1, 32>>>(batch, pBstart);
    {
        dim3 pg(B_BATCH, 8);
        pooled_kernel<<<pg, 256>>>(pX2, out_s, pBstart, pPooled);
    }

    // ---- output MLP ----
    mma_gemm<0,0,1,1,256,256,256,128,128><<<dim3(4, 2), 256, MM_SMEM128>>>(
        pPooled, B_BATCH * S_DIM, nullptr, nullptr, nullptr,
        nullptr, nullptr, pWTO, ob1, pTO);
    out2_kernel<<<B_BATCH * S_DIM, 128>>>(pTO, ow2, ob2, out_latent);
}

// round 17
// speedup vs baseline: 1.5632x; 1.0246x over previous
#include <cuda_runtime.h>
#include <cstdint>

// Problem constants
#define N_NODES 20000
#define N_EDGES 320000
#define F_IN    64
#define H_DIM   256
#define S_DIM   32
#define L_DIM   128
#define B_BATCH 16
#define EPSF    1e-9f

// ===================== helpers =====================
__device__ __forceinline__ uint32_t smem_u32(const void* p) {
    uint32_t a;
    asm("{ .reg .u64 t; cvta.to.shared.u64 t, %1; cvt.u32.u64 %0, t; }" : "=r"(a) : "l"(p));
    return a;
}
__device__ __forceinline__ uint32_t f2tf32(float f) {
    uint32_t r;
    asm("cvt.rna.tf32.f32 %0, %1;" : "=r"(r) : "f"(f));
    return r;
}
__device__ __forceinline__ void mma8(float* c, const uint32_t* a, uint32_t b0, uint32_t b1) {
    asm volatile(
        "mma.sync.aligned.m16n8k8.row.col.f32.tf32.tf32.f32 "
        "{%0,%1,%2,%3}, {%4,%5,%6,%7}, {%8,%9}, {%0,%1,%2,%3};"
        : "+f"(c[0]), "+f"(c[1]), "+f"(c[2]), "+f"(c[3])
        : "r"(a[0]), "r"(a[1]), "r"(a[2]), "r"(a[3]), "r"(b0), "r"(b1));
}
__device__ __forceinline__ void ldsm4(uint32_t* r, uint32_t addr) {
    asm volatile("ldmatrix.sync.aligned.m8n8.x4.shared.b16 {%0,%1,%2,%3}, [%4];"
                 : "=r"(r[0]), "=r"(r[1]), "=r"(r[2]), "=r"(r[3]) : "r"(addr));
}
__device__ __forceinline__ void red2(float* addr, float v0, float v1) {
    asm volatile("red.global.add.v2.f32 [%0], {%1, %2};"
                 :: "l"(addr), "f"(v0), "f"(v1) : "memory");
}

// ===================== device scratch =====================
__device__ float d_XAB[(size_t)N_NODES * 512];   // [n][0:256]=XA, [256:512]=XB
__device__ float d_HS1[N_NODES * H_DIM];
__device__ float d_HS2[N_NODES * H_DIM];
__device__ float d_ACC[N_NODES * H_DIM];
__device__ float d_XLN[N_NODES * H_DIM];
__device__ float d_X2[N_NODES * H_DIM];
__device__ float d_T1[N_NODES * H_DIM];
__device__ float d_LG[N_NODES * S_DIM];
__device__ float d_degf[N_NODES];
__device__ float d_pooled[B_BATCH * S_DIM * H_DIM];
__device__ float d_TO[B_BATCH * S_DIM * H_DIM];
__device__ float d_colsum[S_DIM];
__device__ float d_entsum[1];
__device__ int   d_bstart[B_BATCH + 1];
// transposed (tf32-rounded) weights [outN][K]
__device__ float d_WT1[512 * 64];     // layer-1 w1 (both halves)
__device__ float d_WT2[256 * 256];
__device__ float d_WT3[256 * 256];
__device__ float d_WT4[512 * 256];    // layer-2 w1 (both halves)
__device__ float d_WT5[256 * 256];
__device__ float d_WT6[256 * 256];
__device__ float d_WTA[256 * 256];
__device__ float d_WTO[256 * 256];

// ===================== fused zero =====================
struct ZeroPars { float* p[6]; int n[6]; };
__global__ void zero_all(ZeroPars zp) {
    int r = blockIdx.y;
    float* p = zp.p[r];
    int n = zp.n[r];
    int i = blockIdx.x * blockDim.x + threadIdx.x;
    int st = gridDim.x * blockDim.x;
    for (; i < n; i += st) p[i] = 0.f;
}

__global__ void deg_kernel(const int* __restrict__ dst, float* __restrict__ degf) {
    int i = blockIdx.x * blockDim.x + threadIdx.x;
    int st = gridDim.x * blockDim.x;
    for (; i < N_EDGES; i += st) atomicAdd(&degf[dst[i]], 1.f);
}

// ===================== batched transpose (tf32 round) =====================
struct TransPars { const float* src[10]; float* dst[10]; int R[10]; };
__global__ void transpose_all(TransPars tp) {
    __shared__ float t[32][33];
    int m = blockIdx.z;
    const float* in = tp.src[m];
    float* out = tp.dst[m];
    int R = tp.R[m];
    int c0 = blockIdx.x * 32, r0 = blockIdx.y * 32;
    if (r0 >= R) return;
    for (int j = threadIdx.y; j < 32; j += 8) {
        int r = r0 + j, c = c0 + threadIdx.x;
        t[j][threadIdx.x] = (r < R) ? in[(size_t)r * 256 + c] : 0.f;
    }
    __syncthreads();
    for (int j = threadIdx.y; j < 32; j += 8) {
        int oc = c0 + j, orr = r0 + threadIdx.x;
        if (orr < R)
            out[(size_t)oc * R + orr] = __uint_as_float(f2tf32(t[threadIdx.x][j]));
    }
}

// ===================== tf32 mma.sync GEMM (2-stage, R9 schedule) ==============
// CTA tile MTILE(M) x NTILE(N), grid.y picks the NTILE-col block. K chunks of 32.
// 8 warps: WM_CNT = MTILE/32 M-warps x (8/WM_CNT) N-warps, warp n-width WNW.
// GATHER: A row = relu(XA[gdst*XSTR] + XB[gsrc*XSTR] + bpre).
// SCATTER: epilogue red.v2 into C[gdst].
// Smem stride 36 floats: conflict-free ldmatrix.
// A staging: 8 threads/row x 16B each, MTILE/32 passes (full 128B wavefronts).
template<int GATHER, int SCATTER, int RELU_OUT, int ADD_BIAS, int KLEN,
         int CSTR = 256, int XSTR = 256, int MTILE = 128, int NTILE = 128>
__global__ void __launch_bounds__(256, 2) mma_gemm(
    const float* __restrict__ A, int M,
    const float* __restrict__ XA, const float* __restrict__ XB,
    const float* __restrict__ bpre,
    const int* __restrict__ gsrc, const int* __restrict__ gdst,
    const float* __restrict__ WT,   // [outN][KLEN] K-major, tf32-rounded
    const float* __restrict__ bias,
    float* __restrict__ C)
{
    constexpr int WM_CNT  = MTILE / 32;         // 4 or 2
    constexpr int WN_CNT  = 8 / WM_CNT;         // 2 or 4
    constexpr int WNW     = NTILE / WN_CNT;     // warp n-width (64 here)
    constexpr int NT      = WNW / 8;            // 8
    constexpr int PASSES  = MTILE / 32;         // A staging passes (8 thr/row)
    constexpr int BROWS   = NTILE / 128;        // B row-groups per thread: 1 or 2
    constexpr int ASLOT_A = MTILE * 36;
    constexpr int ASLOT_B = NTILE * 36;

    extern __shared__ float sm[];
    float* sA = sm;                           // 2 * ASLOT_A
    float* sB = sm + 2 * ASLOT_A;             // 2 * ASLOT_B
    int* sdst = (int*)(sm + 2 * ASLOT_A + 2 * ASLOT_B);
    int* ssrc = sdst + MTILE;

    const int tid  = threadIdx.x;
    const int lane = tid & 31;
    const int wid  = tid >> 5;
    const int wm = wid % WM_CNT;
    const int wn = wid / WM_CNT;
    const int lr = lane >> 2;
    const int lc = lane & 3;
    const int row0 = blockIdx.x * MTILE;
    const int col0 = blockIdx.y * NTILE;
    constexpr int NCH = KLEN / 32;

    if ((GATHER || SCATTER) && tid < MTILE) {
        sdst[tid] = gdst[row0 + tid];
        if (GATHER) ssrc[tid] = gsrc[row0 + tid];
    }
    if (GATHER || SCATTER) __syncthreads();

    // A staging mapping: 8 threads per row, 16B (4 floats) per thread.
    const int srow = tid >> 3;    // 0..31 (row within pass)
    const int sseg = tid & 7;     // 0..7 (16B segment within 128B chunk-row)
    const int bn   = tid >> 1;
    const int bkh  = (tid & 1) << 4;
    const uint32_t sA_addr = smem_u32(sA);
    const uint32_t sB_addr = smem_u32(sB);
    const float* WTb = WT + (size_t)(col0 + bn) * KLEN + bkh;

    // ldmatrix per-thread base byte offsets (group = lane>>3, rif = lane&7)
    const int grp = lane >> 3;
    const int rif = lane & 7;
    const uint32_t aLdm = sA_addr
        + (uint32_t)(wm * 32 + (grp & 1) * 8 + rif) * 144u + (uint32_t)(grp >> 1) * 16u;
    const uint32_t bLdm = sB_addr
        + (uint32_t)(wn * WNW + (grp >> 1) * 8 + rif) * 144u + (uint32_t)(grp & 1) * 16u;

    float4 ra[PASSES], rb4[PASSES];

#define ISSUE_B(c, buf)                                                          \
    do {                                                                         \
        _Pragma("unroll")                                                        \
        for (int rr = 0; rr < BROWS; rr++) {                                     \
            uint32_t dstb = sB_addr                                              \
                + (uint32_t)((buf) * ASLOT_B + (bn + rr * 128) * 36 + bkh) * 4u; \
            const float* srcb = WTb + (size_t)rr * 128 * KLEN + (c) * 32;        \
            _Pragma("unroll")                                                    \
            for (int i = 0; i < 4; i++)                                          \
                asm volatile("cp.async.cg.shared.global [%0], [%1], 16;" ::      \
                             "r"(dstb + (uint32_t)i * 16u), "l"(srcb + i * 4) : "memory"); \
        }                                                                        \
        asm volatile("cp.async.commit_group;" ::: "memory");                     \
    } while (0)

#define LOAD_A(c)                                                                \
    do {                                                                         \
        int kg = (c) * 32 + sseg * 4;                                            \
        _Pragma("unroll")                                                        \
        for (int p = 0; p < PASSES; p++) {                                       \
            int row = p * 32 + srow;                                             \
            if (GATHER) {                                                        \
                ra[p]  = *(const float4*)(XA + (size_t)sdst[row] * XSTR + kg);   \
                rb4[p] = *(const float4*)(XB + (size_t)ssrc[row] * XSTR + kg);   \
            } else {                                                             \
                int rg = row0 + row;                                             \
                ra[p] = (rg < M) ? *(const float4*)(A + (size_t)rg * KLEN + kg)  \
                                 : make_float4(0.f, 0.f, 0.f, 0.f);              \
            }                                                                    \
        }                                                                        \
    } while (0)

#define STS_A(c, buf)                                                            \
    do {                                                                         \
        int kg = (c) * 32 + sseg * 4;                                            \
        _Pragma("unroll")                                                        \
        for (int p = 0; p < PASSES; p++) {                                       \
            int row = p * 32 + srow;                                             \
            float4 v = ra[p];                                                    \
            if (GATHER) {                                                        \
                float4 vb = rb4[p];                                              \
                float4 vc = *(const float4*)(bpre + kg);                         \
                v.x = fmaxf(v.x + vb.x + vc.x, 0.f);                             \
                v.y = fmaxf(v.y + vb.y + vc.y, 0.f);                             \
                v.z = fmaxf(v.z + vb.z + vc.z, 0.f);                             \
                v.w = fmaxf(v.w + vb.w + vc.w, 0.f);                             \
            }                                                                    \
            float4 o;                                                            \
            o.x = __uint_as_float(f2tf32(v.x));                                  \
            o.y = __uint_as_float(f2tf32(v.y));                                  \
            o.z = __uint_as_float(f2tf32(v.z));                                  \
            o.w = __uint_as_float(f2tf32(v.w));                                  \
            *(float4*)(sA + (buf) * ASLOT_A + row * 36 + sseg * 4) = o;          \
        }                                                                        \
    } while (0)

    float acc[2][NT][4];
#pragma unroll
    for (int mt = 0; mt < 2; mt++)
#pragma unroll
        for (int nt = 0; nt < NT; nt++)
#pragma unroll
            for (int j = 0; j < 4; j++) acc[mt][nt][j] = 0.f;

    // prologue
    ISSUE_B(0, 0);
    LOAD_A(0);
    STS_A(0, 0);

#pragma unroll
    for (int c = 0; c < NCH; c++) {
        const int buf = c & 1;
        asm volatile("cp.async.wait_group 0;" ::: "memory");
        __syncthreads();
        if (c + 1 < NCH) {
            ISSUE_B(c + 1, buf ^ 1);
            LOAD_A(c + 1);
        }
        // mma over chunk c (ldmatrix fragment loads)
        const uint32_t aB = aLdm + (uint32_t)(buf * ASLOT_A * 4);
        const uint32_t bB = bLdm + (uint32_t)(buf * ASLOT_B * 4);
#pragma unroll
        for (int ks = 0; ks < 4; ks++) {
            uint32_t a0[4], a1[4];
            ldsm4(a0, aB + (uint32_t)ks * 32u);
            ldsm4(a1, aB + 16u * 144u + (uint32_t)ks * 32u);
#pragma unroll
            for (int ntp = 0; ntp < NT / 2; ntp++) {
                uint32_t b[4];
                ldsm4(b, bB + (uint32_t)ntp * 16u * 144u + (uint32_t)ks * 32u);
                mma8(acc[0][2 * ntp + 0], a0, b[0], b[1]);
                mma8(acc[1][2 * ntp + 0], a1, b[0], b[1]);
                mma8(acc[0][2 * ntp + 1], a0, b[2], b[3]);
                mma8(acc[1][2 * ntp + 1], a1, b[2], b[3]);
            }
        }
        if (c + 1 < NCH) STS_A(c + 1, buf ^ 1);
    }

    // ---- epilogue ----
#pragma unroll
    for (int mt = 0; mt < 2; mt++) {
#pragma unroll
        for (int part = 0; part < 2; part++) {
            const int rloc = wm * 32 + mt * 16 + lr + part * 8;
            const int rg = row0 + rloc;
            if (!(GATHER || SCATTER) && rg >= M) continue;
            float* outp = SCATTER ? (C + (size_t)sdst[rloc] * 256)
                                  : (C + (size_t)rg * CSTR);
#pragma unroll
            for (int nt = 0; nt < NT; nt++) {
                const int col = col0 + wn * WNW + nt * 8 + 2 * lc;
                float v0 = acc[mt][nt][part * 2 + 0];
                float v1 = acc[mt][nt][part * 2 + 1];
                if (ADD_BIAS) { v0 += bias[col]; v1 += bias[col + 1]; }
                if (RELU_OUT) { v0 = fmaxf(v0, 0.f); v1 = fmaxf(v1, 0.f); }
                if (SCATTER) {
                    red2(outp + col, v0, v1);
                } else {
                    *(float2*)(outp + col) = make_float2(v0, v1);
                }
            }
        }
    }
}

static constexpr size_t MM_SMEM128 = 2u * (128 * 36 + 128 * 36) * 4u + 1024u;  // 74752
static constexpr size_t MM_SMEM_E  = 2u * (64 * 36 + 256 * 36) * 4u + 1024u;   // 93184

// ---------------- relu + layernorm with deg*b3 pre-add ----------------
__global__ void relu_ln_kernel(const float* __restrict__ IN,
                               const float* __restrict__ degf, const float* __restrict__ b3,
                               const float* __restrict__ g, const float* __restrict__ b,
                               float* __restrict__ OUT)
{
    int gid = blockIdx.x * blockDim.x + threadIdx.x;
    int node = gid >> 5;
    int lane = gid & 31;
    if (node >= N_NODES) return;
    const float* x = &IN[(size_t)node * 256];
    float dg = degf[node];
    float v[8];
    float s = 0.f;
#pragma unroll
    for (int q = 0; q < 2; q++) {
        float4 t = *(const float4*)(&x[lane * 8 + q * 4]);
        float4 bb = *(const float4*)(&b3[lane * 8 + q * 4]);
        v[q * 4 + 0] = fmaxf(fmaf(dg, bb.x, t.x), 0.f);
        v[q * 4 + 1] = fmaxf(fmaf(dg, bb.y, t.y), 0.f);
        v[q * 4 + 2] = fmaxf(fmaf(dg, bb.z, t.z), 0.f);
        v[q * 4 + 3] = fmaxf(fmaf(dg, bb.w, t.w), 0.f);
    }
#pragma unroll
    for (int i = 0; i < 8; i++) s += v[i];
#pragma unroll
    for (int o = 16; o > 0; o >>= 1) s += __shfl_xor_sync(0xffffffffu, s, o);
    float mu = s * (1.f / 256.f);
    float vs = 0.f;
#pragma unroll
    for (int i = 0; i < 8; i++) { float d = v[i] - mu; vs += d * d; }
#pragma unroll
    for (int o = 16; o > 0; o >>= 1) vs += __shfl_xor_sync(0xffffffffu, vs, o);
    float inv = rsqrtf(vs * (1.f / 256.f) + 1e-5f);
#pragma unroll
    for (int i = 0; i < 8; i++) {
        int c = lane * 8 + i;
        OUT[(size_t)node * 256 + c] = (v[i] - mu) * inv * g[c] + b[c];
    }
}

// ---------------- logits = T1 @ aw2 + ab2 (N x 32) ----------------
__global__ void logits_kernel(const float* __restrict__ T1, const float* __restrict__ aw2,
                              const float* __restrict__ ab2, float* __restrict__ LG)
{
    int c = threadIdx.x;
    int n = blockIdx.x * blockDim.y + threadIdx.y;
    if (n >= N_NODES) return;
    const float* t = &T1[(size_t)n * 256];
    float acc = ab2[c];
#pragma unroll 8
    for (int k = 0; k < 256; k++) acc = fmaf(t[k], aw2[k * 32 + c], acc);
    LG[n * 32 + c] = acc;
}

// ---------------- gumbel softmax + loss partials ----------------
__global__ void gumbel_kernel(const float* __restrict__ LG, const float* __restrict__ U,
                              float* __restrict__ sOut, float* __restrict__ colsum,
                              float* __restrict__ entsum)
{
    int lane = threadIdx.x & 31;
    int gw = (blockIdx.x * blockDim.x + threadIdx.x) >> 5;
    int nw = (gridDim.x * blockDim.x) >> 5;
    float colAcc = 0.f, entAcc = 0.f;
    for (int n = gw; n < N_NODES; n += nw) {
        float u = U[n * 32 + lane];
        float gn = -logf(-logf(u + EPSF) + EPSF);
        float v = LG[n * 32 + lane] + gn;
        float mx = v;
#pragma unroll
        for (int o = 16; o > 0; o >>= 1) mx = fmaxf(mx, __shfl_xor_sync(0xffffffffu, mx, o));
        float e = expf(v - mx);
        float ssum = e;
#pragma unroll
        for (int o = 16; o > 0; o >>= 1) ssum += __shfl_xor_sync(0xffffffffu, ssum, o);
        float sv = e / ssum;
        sOut[n * 32 + lane] = sv;
        colAcc += sv;
        entAcc += sv * logf(sv + EPSF);
    }
    atomicAdd(&colsum[lane], colAcc);
#pragma unroll
    for (int o = 16; o > 0; o >>= 1) entAcc += __shfl_xor_sync(0xffffffffu, entAcc, o);
    if (lane == 0) atomicAdd(entsum, entAcc);
}

__global__ void loss_kernel(const float* __restrict__ colsum, const float* __restrict__ entsum,
                            float* __restrict__ outLoss)
{
    int lane = threadIdx.x;
    float avg = colsum[lane] * (1.f / (float)N_NODES);
    float dv = avg * logf(avg + EPSF);
#pragma unroll
    for (int o = 16; o > 0; o >>= 1) dv += __shfl_xor_sync(0xffffffffu, dv, o);
    if (lane == 0) outLoss[0] = dv - entsum[0] * (1.f / (float)N_NODES);
}

__global__ void bounds_kernel(const int* __restrict__ batch, int* __restrict__ bstart)
{
    int t = threadIdx.x;
    if (t > B_BATCH) return;
    int lo = 0, hi = N_NODES;
    while (lo < hi) {
        int mid = (lo + hi) >> 1;
        if (batch[mid] < t) lo = mid + 1; else hi = mid;
    }
    bstart[t] = lo;
}

__global__ void pooled_kernel(const float* __restrict__ X2, const float* __restrict__ S,
                              const int* __restrict__ bstart, float* __restrict__ pooled)
{
    int b = blockIdx.x;
    int nchunk = gridDim.y;
    int s0 = bstart[b], s1 = bstart[b + 1];
    int len = s1 - s0;
    int per = (len + nchunk - 1) / nchunk;
    int n0 = s0 + blockIdx.y * per;
    int n1 = min(n0 + per, s1);
    if (n0 >= n1) return;

    int h = threadIdx.x;
    float acc[32];
#pragma unroll
    for (int k = 0; k < 32; k++) acc[k] = 0.f;

    __shared__ float st[8][33];
    for (int basei = n0; basei < n1; basei += 8) {
        __syncthreads();
        {
            int rr = threadIdx.x >> 5, cc = threadIdx.x & 31;
            st[rr][cc] = (basei + rr < n1) ? S[(size_t)(basei + rr) * 32 + cc] : 0.f;
        }
        __syncthreads();
        int cnt = min(8, n1 - basei);
        for (int rr = 0; rr < cnt; rr++) {
            float xv = X2[(size_t)(basei + rr) * 256 + h];
#pragma unroll
            for (int k = 0; k < 32; k++) acc[k] = fmaf(st[rr][k], xv, acc[k]);
        }
    }
#pragma unroll
    for (int k = 0; k < 32; k++)
        atomicAdd(&pooled[((size_t)b * 32 + k) * 256 + h], acc[k]);
}

__global__ void out2_kernel(const float* __restrict__ TO, const float* __restrict__ ow2,
                            const float* __restrict__ ob2, float* __restrict__ out)
{
    int r = blockIdx.x;
    int c = threadIdx.x;
    const float* t = &TO[(size_t)r * 256];
    float acc = ob2[c];
#pragma unroll 8
    for (int k = 0; k < 256; k++) acc = fmaf(t[k], ow2[k * 128 + c], acc);
    out[(size_t)r * 128 + c] = acc;
}

// ===================== launch =====================
extern "C" void kernel_launch(void* const* d_in, const int* in_sizes, int n_in,
                              void* d_out, int out_size)
{
    const float* x    = (const float*)d_in[0];
    const float* u    = (const float*)d_in[1];
    const int*   ei   = (const int*)d_in[2];
    const int*   batch= (const int*)d_in[3];
    const float* g1w1 = (const float*)d_in[4];
    const float* g1b1 = (const float*)d_in[5];
    const float* g1w2 = (const float*)d_in[6];
    const float* g1b2 = (const float*)d_in[7];
    const float* g1w3 = (const float*)d_in[8];
    const float* g1b3 = (const float*)d_in[9];
    const float* ln1g = (const float*)d_in[10];
    const float* ln1b = (const float*)d_in[11];
    const float* g2w1 = (const float*)d_in[12];
    const float* g2b1 = (const float*)d_in[13];
    const float* g2w2 = (const float*)d_in[14];
    const float* g2b2 = (const float*)d_in[15];
    const float* g2w3 = (const float*)d_in[16];
    const float* g2b3 = (const float*)d_in[17];
    const float* ln2g = (const float*)d_in[18];
    const float* ln2b = (const float*)d_in[19];
    const float* aw1  = (const float*)d_in[20];
    const float* ab1  = (const float*)d_in[21];
    const float* aw2  = (const float*)d_in[22];
    const float* ab2  = (const float*)d_in[23];
    const float* ow1  = (const float*)d_in[24];
    const float* ob1  = (const float*)d_in[25];
    const float* ow2  = (const float*)d_in[26];
    const float* ob2  = (const float*)d_in[27];

    const int* srcI = ei;
    const int* dstI = ei + N_EDGES;

    float* out        = (float*)d_out;
    float* out_latent = out;
    float* out_s      = out + B_BATCH * S_DIM * L_DIM;
    float* out_loss   = out_s + (size_t)N_NODES * S_DIM;

    float *pXAB, *pHS1, *pHS2, *pACC, *pXLN, *pX2, *pT1, *pLG, *pDeg, *pPooled, *pTO, *pColsum, *pEntsum;
    float *pWT1, *pWT2, *pWT3, *pWT4, *pWT5, *pWT6, *pWTA, *pWTO;
    int* pBstart;
    cudaGetSymbolAddress((void**)&pXAB, d_XAB);
    cudaGetSymbolAddress((void**)&pHS1, d_HS1);
    cudaGetSymbolAddress((void**)&pHS2, d_HS2);
    cudaGetSymbolAddress((void**)&pACC, d_ACC);
    cudaGetSymbolAddress((void**)&pXLN, d_XLN);
    cudaGetSymbolAddress((void**)&pX2, d_X2);
    cudaGetSymbolAddress((void**)&pT1, d_T1);
    cudaGetSymbolAddress((void**)&pLG, d_LG);
    cudaGetSymbolAddress((void**)&pDeg, d_degf);
    cudaGetSymbolAddress((void**)&pPooled, d_pooled);
    cudaGetSymbolAddress((void**)&pTO, d_TO);
    cudaGetSymbolAddress((void**)&pColsum, d_colsum);
    cudaGetSymbolAddress((void**)&pEntsum, d_entsum);
    cudaGetSymbolAddress((void**)&pBstart, d_bstart);
    cudaGetSymbolAddress((void**)&pWT1, d_WT1);
    cudaGetSymbolAddress((void**)&pWT2, d_WT2);
    cudaGetSymbolAddress((void**)&pWT3, d_WT3);
    cudaGetSymbolAddress((void**)&pWT4, d_WT4);
    cudaGetSymbolAddress((void**)&pWT5, d_WT5);
    cudaGetSymbolAddress((void**)&pWT6, d_WT6);
    cudaGetSymbolAddress((void**)&pWTA, d_WTA);
    cudaGetSymbolAddress((void**)&pWTO, d_WTO);

    cudaFuncSetAttribute(mma_gemm<0,0,0,0,64,512,256,128,128>,  cudaFuncAttributeMaxDynamicSharedMemorySize, (int)MM_SMEM128);
    cudaFuncSetAttribute(mma_gemm<1,1,1,1,256,256,512,64,256>,  cudaFuncAttributeMaxDynamicSharedMemorySize, (int)MM_SMEM_E);
    cudaFuncSetAttribute(mma_gemm<0,0,0,0,256,256,256,128,128>, cudaFuncAttributeMaxDynamicSharedMemorySize, (int)MM_SMEM128);
    cudaFuncSetAttribute(mma_gemm<0,0,0,0,256,512,256,128,128>, cudaFuncAttributeMaxDynamicSharedMemorySize, (int)MM_SMEM128);
    cudaFuncSetAttribute(mma_gemm<0,0,1,1,256,256,256,128,128>, cudaFuncAttributeMaxDynamicSharedMemorySize, (int)MM_SMEM128);

    const dim3 GN((N_NODES + 127) / 128, 2);    // 157 x 2
    const dim3 GN4((N_NODES + 127) / 128, 4);   // 157 x 4 (XAB producer)
    const dim3 GE(N_EDGES / 64, 1);             // 5000 x 1 (M=64, N=256 edge tiles)

    // ---- fused zeroing + degree + all weight transposes ----
    {
        ZeroPars zp;
        zp.p[0] = pHS1;    zp.n[0] = N_NODES * H_DIM;
        zp.p[1] = pHS2;    zp.n[1] = N_NODES * H_DIM;
        zp.p[2] = pDeg;    zp.n[2] = N_NODES;
        zp.p[3] = pColsum; zp.n[3] = S_DIM;
        zp.p[4] = pEntsum; zp.n[4] = 1;
        zp.p[5] = pPooled; zp.n[5] = B_BATCH * S_DIM * H_DIM;
        zero_all<<<dim3(160, 6), 256>>>(zp);
    }
    deg_kernel<<<256, 256>>>(dstI, pDeg);
    {
        TransPars tp;
        tp.src[0] = g1w1;             tp.dst[0] = pWT1;            tp.R[0] = 64;
        tp.src[1] = g1w1 + 64 * 256;  tp.dst[1] = pWT1 + 256 * 64; tp.R[1] = 64;
        tp.src[2] = g1w2;             tp.dst[2] = pWT2;            tp.R[2] = 256;
        tp.src[3] = g1w3;             tp.dst[3] = pWT3;            tp.R[3] = 256;
        tp.src[4] = g2w1;             tp.dst[4] = pWT4;            tp.R[4] = 256;
        tp.src[5] = g2w1 + 256 * 256; tp.dst[5] = pWT4 + 256 * 256;tp.R[5] = 256;
        tp.src[6] = g2w2;             tp.dst[6] = pWT5;            tp.R[6] = 256;
        tp.src[7] = g2w3;             tp.dst[7] = pWT6;            tp.R[7] = 256;
        tp.src[8] = aw1;              tp.dst[8] = pWTA;            tp.R[8] = 256;
        tp.src[9] = ow1;              tp.dst[9] = pWTO;            tp.R[9] = 256;
        dim3 tg(8, 8, 10), tb(32, 8);
        transpose_all<<<tg, tb>>>(tp);
    }

    // ---- layer 1 ----
    mma_gemm<0,0,0,0,64,512,256,128,128><<<GN4, 256, MM_SMEM128>>>(
        x, N_NODES, nullptr, nullptr, nullptr, nullptr, nullptr, pWT1, nullptr, pXAB);
    mma_gemm<1,1,1,1,256,256,512,64,256><<<GE, 256, MM_SMEM_E>>>(
        nullptr, N_EDGES, pXAB, pXAB + 256, g1b1, srcI, dstI, pWT2, g1b2, pHS1);
    mma_gemm<0,0,0,0,256,256,256,128,128><<<GN, 256, MM_SMEM128>>>(
        pHS1, N_NODES, nullptr, nullptr, nullptr, nullptr, nullptr, pWT3, nullptr, pACC);
    relu_ln_kernel<<<(N_NODES * 32 + 255) / 256, 256>>>(pACC, pDeg, g1b3, ln1g, ln1b, pXLN);

    // ---- layer 2 ----
    mma_gemm<0,0,0,0,256,512,256,128,128><<<GN4, 256, MM_SMEM128>>>(
        pXLN, N_NODES, nullptr, nullptr, nullptr, nullptr, nullptr, pWT4, nullptr, pXAB);
    mma_gemm<1,1,1,1,256,256,512,64,256><<<GE, 256, MM_SMEM_E>>>(
        nullptr, N_EDGES, pXAB, pXAB + 256, g2b1, srcI, dstI, pWT5, g2b2, pHS2);
    mma_gemm<0,0,0,0,256,256,256,128,128><<<GN, 256, MM_SMEM128>>>(
        pHS2, N_NODES, nullptr, nullptr, nullptr, nullptr, nullptr, pWT6, nullptr, pACC);
    relu_ln_kernel<<<(N_NODES * 32 + 255) / 256, 256>>>(pACC, pDeg, g2b3, ln2g, ln2b, pX2);

    // ---- assignment ----
    mma_gemm<0,0,1,1,256,256,256,128,128><<<GN, 256, MM_SMEM128>>>(
        pX2, N_NODES, nullptr, nullptr, nullptr, nullptr, nullptr, pWTA, ab1, pT1);
    {
        dim3 lb(32, 8);
        logits_kernel<<<(N_NODES + 7) / 8, lb>>>(pT1, aw2, ab2, pLG);
    }
    gumbel_kernel<<<160, 256>>>(pLG, u, out_s, pColsum, pEntsum);
    loss_kernel<<<1, 32>>>(pColsum, pEntsum, out_loss);

    // ---- pooling ----
    bounds_kernel<<<1, 32>>>(batch, pBstart);
    {
        dim3 pg(B_BATCH, 16);
        pooled_kernel<<<pg, 256>>>(pX2, out_s, pBstart, pPooled);
    }

    // ---- output MLP ----
    mma_gemm<0,0,1,1,256,256,256,128,128><<<dim3(4, 2), 256, MM_SMEM128>>>(
        pPooled, B_BATCH * S_DIM, nullptr, nullptr, nullptr,
        nullptr, nullptr, pWTO, ob1, pTO);
    out2_kernel<<<B_BATCH * S_DIM, 128>>>(pTO, ow2, ob2, out_latent);
}